// round 6
// baseline (speedup 1.0000x reference)
#include <cuda_runtime.h>
#include <math.h>

#define NB 100
#define NPG 500
#define EPG 8000
#define F_IN 64
#define HEADS 4
#define DH 16
#define EMB 64
#define HID 256
#define NTH 512
#define SPLIT 3
#define BCAP 24      // bucket capacity per dst per split (Poisson(5.33); P(>=24) ~ 3e-12)

// ---------------- global scratch ----------------
__device__ float g_part[NB * SPLIT * NPG * 8];   // den4 + acc4 per (graph, split, dst)
__device__ float g_bc[NB];                       // bias . msg_emb per graph

// ---------------- kernel1 smem layout (float words) ----------------
#define OFF_WS 0                    // wsH[4*68]
#define OFF_WD 272                  // wdH[4*68]
#define OFF_WT 544                  // wtH[4*68]
#define OFF_ME 816                  // me[64]
#define OFF_BC 880                  // bconst[1] (+pad)
#define OFF_AS 884                  // A_s4f[2000]
#define OFF_AD 2884                 // A_d4f[2000]
#define OFF_T  4884                 // T4f[2000]
#define OFF_CUR 6884                // cur[500] int
#define OFF_BUCK 7384               // buckets ushort[500*24] = 6000 words
#define OFF_XS 13384                // xs[64*68] = 4352 words
#define SMEM_WORDS (OFF_XS + 4352)
#define SMEM_BYTES (SMEM_WORDS * 4)

extern __shared__ float smem[];

__global__ void __launch_bounds__(NTH, 2)
part_kernel(const float* __restrict__ message,
            const float* __restrict__ x,
            const int* __restrict__ esrc,
            const int* __restrict__ edst,
            const float* __restrict__ W,
            const float* __restrict__ a_src,
            const float* __restrict__ a_dst,
            const float* __restrict__ bias,
            const float* __restrict__ fc_w,
            const float* __restrict__ fc_b) {
    const int b = blockIdx.x / SPLIT;
    const int split = blockIdx.x - b * SPLIT;
    const int nbase = b * NPG;
    const int ebase = b * EPG;
    const int tid = threadIdx.x;

    float* wsH = smem + OFF_WS;
    float* wdH = smem + OFF_WD;
    float* wtH = smem + OFF_WT;
    float* me = smem + OFF_ME;
    float* A_s4f = smem + OFF_AS;
    float* A_d4f = smem + OFF_AD;
    float* T4f = smem + OFF_T;
    int* cur = (int*)(smem + OFF_CUR);
    unsigned short* buck = (unsigned short*)(smem + OFF_BUCK);
    float* xs = smem + OFF_XS;

    if (tid < 256) {
        // ============== GEMM side: warps 0-7 ==============
        // me[c] = fc_w[c,:] . message[b,:] + fc_b[c]
        {
            const int c = tid >> 2;        // 0..63
            const int p = tid & 3;         // quarter of HID
            const float4* wr = (const float4*)(fc_w + c * HID + p * 64);
            const float4* mr = (const float4*)(message + b * HID + p * 64);
            float acc = 0.0f;
#pragma unroll
            for (int i = 0; i < 16; i++) {
                float4 w = wr[i]; float4 m = mr[i];
                acc += w.x * m.x + w.y * m.y + w.z * m.z + w.w * m.w;
            }
            acc += __shfl_xor_sync(0xffffffffu, acc, 1);
            acc += __shfl_xor_sync(0xffffffffu, acc, 2);
            if (p == 0) me[c] = acc + fc_b[c];
        }
        asm volatile("bar.sync 1, 256;" ::: "memory");

        // folded weight vectors
        {
            const int f = tid >> 2, hh = tid & 3;
            const float* wrow = W + (f * HEADS + hh) * DH;
            const float* av = a_src + hh * DH;
            const float* dv = a_dst + hh * DH;
            const float* mv = me + hh * DH;
            float s = 0.f, d = 0.f, t = 0.f;
#pragma unroll
            for (int k = 0; k < DH; k++) {
                float wv = wrow[k];
                s += wv * av[k]; d += wv * dv[k]; t += wv * mv[k];
            }
            wsH[hh * 68 + f] = s;
            wdH[hh * 68 + f] = d;
            wtH[hh * 68 + f] = t;
        }
        asm volatile("bar.sync 1, 256;" ::: "memory");

        // bconst = bias . me (warp 0) -> smem + global (all splits write same value)
        if (tid < 32) {
            float v = bias[tid] * me[tid] + bias[tid + 32] * me[tid + 32];
#pragma unroll
            for (int o = 16; o > 0; o >>= 1) v += __shfl_xor_sync(0xffffffffu, v, o);
            if (tid == 0) { smem[OFF_BC] = v; g_bc[b] = v; }
        }

        // As/Ad/T mini-GEMM, 8 chunks of 64 nodes
        for (int c = 0; c < 8; c++) {
            const int rbase = c * 64;
            const int nrow = (c == 7) ? (NPG - 448) : 64;   // 52 last
            for (int i = tid; i < nrow * 16; i += 256) {
                int r = i >> 4, f4 = i & 15;
                *(float4*)&xs[r * 68 + f4 * 4] =
                    ((const float4*)x)[(size_t)(nbase + rbase + r) * 16 + f4];
            }
            asm volatile("bar.sync 1, 256;" ::: "memory");
            const int n = tid >> 2, hh = tid & 3;
            if (n < nrow) {
                float as = 0.f, ad = 0.f, tt = 0.f;
                const float* xr = xs + n * 68;
                const float* pws = wsH + hh * 68;
                const float* pwd = wdH + hh * 68;
                const float* pwt = wtH + hh * 68;
#pragma unroll
                for (int f4 = 0; f4 < 16; f4++) {
                    float4 xv = *(const float4*)(xr + f4 * 4);
                    float4 w1 = *(const float4*)(pws + f4 * 4);
                    float4 w2 = *(const float4*)(pwd + f4 * 4);
                    float4 w3 = *(const float4*)(pwt + f4 * 4);
                    as += xv.x * w1.x + xv.y * w1.y + xv.z * w1.z + xv.w * w1.w;
                    ad += xv.x * w2.x + xv.y * w2.y + xv.z * w2.z + xv.w * w2.w;
                    tt += xv.x * w3.x + xv.y * w3.y + xv.z * w3.z + xv.w * w3.w;
                }
                const int gn = rbase + n;
                A_s4f[gn * 4 + hh] = as;
                A_d4f[gn * 4 + hh] = ad;
                T4f[gn * 4 + hh] = tt;
            }
            asm volatile("bar.sync 1, 256;" ::: "memory");
        }
    } else {
        // ============== Scatter side: warps 8-15, this split's edge range ==============
        const int lt = tid - 256;
        for (int i = lt; i < NPG; i += 256) cur[i] = 0;
        asm volatile("bar.sync 2, 256;" ::: "memory");
        const int e0 = (split * (EPG / 4)) / SPLIT;         // int4 indices
        const int e1 = ((split + 1) * (EPG / 4)) / SPLIT;
        for (int i = e0 + lt; i < e1; i += 256) {
            int4 s4 = ((const int4*)(esrc + ebase))[i];
            int4 d4 = ((const int4*)(edst + ebase))[i];
            int d0 = d4.x - nbase, d1 = d4.y - nbase,
                d2 = d4.z - nbase, d3 = d4.w - nbase;
            int p0 = atomicAdd(&cur[d0], 1);
            if (p0 < BCAP) buck[d0 * BCAP + p0] = (unsigned short)(s4.x - nbase);
            int p1 = atomicAdd(&cur[d1], 1);
            if (p1 < BCAP) buck[d1 * BCAP + p1] = (unsigned short)(s4.y - nbase);
            int p2 = atomicAdd(&cur[d2], 1);
            if (p2 < BCAP) buck[d2 * BCAP + p2] = (unsigned short)(s4.z - nbase);
            int p3 = atomicAdd(&cur[d3], 1);
            if (p3 < BCAP) buck[d3 * BCAP + p3] = (unsigned short)(s4.w - nbase);
        }
    }
    __syncthreads();

    // ---- Gather partials: one thread per dst, 4 heads; write den4+acc4 ----
    if (tid < NPG) {
        const int d = tid;
        int n = cur[d]; n = (n < BCAP) ? n : BCAP;
        const float4 ad4 = *(const float4*)&A_d4f[d * 4];
        const unsigned short* bk = buck + d * BCAP;
        float den0 = 0.f, den1 = 0.f, den2 = 0.f, den3 = 0.f;
        float ac0 = 0.f, ac1 = 0.f, ac2 = 0.f, ac3 = 0.f;
        for (int j = 0; j < n; j++) {
            const int s = bk[j];
            const float4 as4 = *(const float4*)&A_s4f[s * 4];
            const float4 t4 = *(const float4*)&T4f[s * 4];
            float e0 = as4.x + ad4.x; e0 = (e0 > 0.f) ? e0 : 0.2f * e0;
            float e1 = as4.y + ad4.y; e1 = (e1 > 0.f) ? e1 : 0.2f * e1;
            float e2 = as4.z + ad4.z; e2 = (e2 > 0.f) ? e2 : 0.2f * e2;
            float e3 = as4.w + ad4.w; e3 = (e3 > 0.f) ? e3 : 0.2f * e3;
            float x0 = __expf(e0), x1 = __expf(e1), x2 = __expf(e2), x3 = __expf(e3);
            den0 += x0; den1 += x1; den2 += x2; den3 += x3;
            ac0 += x0 * t4.x; ac1 += x1 * t4.y; ac2 += x2 * t4.z; ac3 += x3 * t4.w;
        }
        float* gp = g_part + ((size_t)blockIdx.x * NPG + d) * 8;
        *(float4*)(gp + 0) = make_float4(den0, den1, den2, den3);
        *(float4*)(gp + 4) = make_float4(ac0, ac1, ac2, ac3);
    }
}

// ---------------- kernel2: combine splits + log_softmax ----------------
__global__ void __launch_bounds__(512)
combine_kernel(float* __restrict__ out) {
    const int b = blockIdx.x;
    const int tid = threadIdx.x;
    float v = -INFINITY;
    if (tid < NPG) {
        float den0 = 0.f, den1 = 0.f, den2 = 0.f, den3 = 0.f;
        float ac0 = 0.f, ac1 = 0.f, ac2 = 0.f, ac3 = 0.f;
#pragma unroll
        for (int s = 0; s < SPLIT; s++) {
            const float* gp = g_part + ((size_t)(b * SPLIT + s) * NPG + tid) * 8;
            float4 dn = *(const float4*)(gp + 0);
            float4 ac = *(const float4*)(gp + 4);
            den0 += dn.x; den1 += dn.y; den2 += dn.z; den3 += dn.w;
            ac0 += ac.x; ac1 += ac.y; ac2 += ac.z; ac3 += ac.w;
        }
        float r0 = (den0 > 0.f) ? __fdividef(ac0, den0) : 0.f;
        float r1 = (den1 > 0.f) ? __fdividef(ac1, den1) : 0.f;
        float r2 = (den2 > 0.f) ? __fdividef(ac2, den2) : 0.f;
        float r3 = (den3 > 0.f) ? __fdividef(ac3, den3) : 0.f;
        v = r0 + r1 + r2 + r3 + g_bc[b];
    }

    __shared__ float lred[16];
    float m = v;
#pragma unroll
    for (int o = 16; o > 0; o >>= 1) m = fmaxf(m, __shfl_xor_sync(0xffffffffu, m, o));
    if ((tid & 31) == 0) lred[tid >> 5] = m;
    __syncthreads();
    if (tid < 32) {
        float t = (tid < 16) ? lred[tid] : -INFINITY;
#pragma unroll
        for (int o = 8; o > 0; o >>= 1) t = fmaxf(t, __shfl_xor_sync(0xffffffffu, t, o));
        if (tid == 0) lred[0] = t;
    }
    __syncthreads();
    m = lred[0];
    __syncthreads();
    float p = (tid < NPG) ? __expf(v - m) : 0.0f;
    float s = p;
#pragma unroll
    for (int o = 16; o > 0; o >>= 1) s += __shfl_xor_sync(0xffffffffu, s, o);
    if ((tid & 31) == 0) lred[tid >> 5] = s;
    __syncthreads();
    if (tid < 32) {
        float t = (tid < 16) ? lred[tid] : 0.0f;
#pragma unroll
        for (int o = 8; o > 0; o >>= 1) t += __shfl_xor_sync(0xffffffffu, t, o);
        if (tid == 0) lred[0] = t;
    }
    __syncthreads();
    const float lse = m + logf(lred[0]);
    if (tid < NPG) out[b * NPG + tid] = v - lse;
}

// ---------------- Launch ----------------
extern "C" void kernel_launch(void* const* d_in, const int* in_sizes, int n_in,
                              void* d_out, int out_size) {
    const float* message = (const float*)d_in[0];
    const float* x       = (const float*)d_in[1];
    const int*   esrc    = (const int*)d_in[2];
    const int*   edst    = (const int*)d_in[3];
    const float* W       = (const float*)d_in[4];
    const float* a_src   = (const float*)d_in[5];
    const float* a_dst   = (const float*)d_in[6];
    const float* bias    = (const float*)d_in[7];
    const float* fc_w    = (const float*)d_in[8];
    const float* fc_b    = (const float*)d_in[9];
    float* out = (float*)d_out;

    static int init = 0;
    if (!init) {
        cudaFuncSetAttribute(part_kernel, cudaFuncAttributeMaxDynamicSharedMemorySize, SMEM_BYTES);
        init = 1;
    }

    part_kernel<<<NB * SPLIT, NTH, SMEM_BYTES>>>(message, x, esrc, edst, W,
                                                 a_src, a_dst, bias, fc_w, fc_b);
    combine_kernel<<<NB, 512>>>(out);
}

// round 7
// speedup vs baseline: 2.8336x; 2.8336x over previous
#include <cuda_runtime.h>
#include <math.h>

#define NB 100
#define NPG 500
#define EPG 8000
#define F_IN 64
#define HEADS 4
#define DH 16
#define EMB 64
#define HID 256
#define NTH 512
#define BCAP 50
#define ESPLIT4 1500   // int4-edge groups: scatter warps take [0,1500), GEMM warps join [1500,2000)

// ---------------- smem layout (float words) ----------------
// ws4[64*4]  @0      folded W@a_src, float4 over heads per feature
// wd4[64*4]  @256
// wt4[64*4]  @512
// me[64]     @768
// bc[4]      @832
// A_s4f[2000]@836
// A_d4f[2000]@2836
// T4f[2000]  @4836
// cur[500]   @6836
// buck ushort[500*50] = 12500 words @7336
// xs[500*68] = 34000 words @19836
#define OFF_WS 0
#define OFF_WD 256
#define OFF_WT 512
#define OFF_ME 768
#define OFF_BC 832
#define OFF_AS 836
#define OFF_AD 2836
#define OFF_T  4836
#define OFF_CUR 6836
#define OFF_BUCK 7336
#define OFF_XS 19836
#define SMEM_WORDS (OFF_XS + NPG * 68)
#define SMEM_BYTES (SMEM_WORDS * 4)   // 215,344 B < 227 KB

extern __shared__ float smem[];

__global__ void __launch_bounds__(NTH, 1)
fused_kernel(const float* __restrict__ message,
             const float* __restrict__ x,
             const int* __restrict__ esrc,
             const int* __restrict__ edst,
             const float* __restrict__ W,
             const float* __restrict__ a_src,
             const float* __restrict__ a_dst,
             const float* __restrict__ bias,
             const float* __restrict__ fc_w,
             const float* __restrict__ fc_b,
             float* __restrict__ out) {
    const int b = blockIdx.x;
    const int nbase = b * NPG;
    const int ebase = b * EPG;
    const int tid = threadIdx.x;

    float* me = smem + OFF_ME;
    float* A_s4f = smem + OFF_AS;
    float* A_d4f = smem + OFF_AD;
    float* T4f = smem + OFF_T;
    int* cur = (int*)(smem + OFF_CUR);
    unsigned short* buck = (unsigned short*)(smem + OFF_BUCK);
    float* xs = smem + OFF_XS;

    if (tid < 256) {
        // ================= GEMM side: warps 0-7 =================
        // ---- stage x rows into smem (coalesced), kicked off first ----
        for (int i = tid; i < NPG * 16; i += 256) {
            int r = i >> 4, f4 = i & 15;
            *(float4*)&xs[r * 68 + f4 * 4] =
                ((const float4*)x)[(size_t)(nbase + r) * 16 + f4];
        }

        // ---- Phase A: me[c] = fc_w[c,:] . message[b,:] + fc_b[c] ----
        {
            const int c = tid >> 2;        // 0..63
            const int p = tid & 3;         // quarter of HID
            const float4* wr = (const float4*)(fc_w + c * HID + p * 64);
            const float4* mr = (const float4*)(message + b * HID + p * 64);
            float acc = 0.0f;
#pragma unroll
            for (int i = 0; i < 16; i++) {
                float4 w = wr[i]; float4 m = mr[i];
                acc += w.x * m.x + w.y * m.y + w.z * m.z + w.w * m.w;
            }
            acc += __shfl_xor_sync(0xffffffffu, acc, 1);
            acc += __shfl_xor_sync(0xffffffffu, acc, 2);
            if (p == 0) me[c] = acc + fc_b[c];
        }
        asm volatile("bar.sync 1, 256;" ::: "memory");

        // ---- Phase B: folded weights, layout float4-over-heads per feature ----
        {
            const int f = tid >> 2, hh = tid & 3;
            const float* wrow = W + (f * HEADS + hh) * DH;
            const float* av = a_src + hh * DH;
            const float* dv = a_dst + hh * DH;
            const float* mv = me + hh * DH;
            float s = 0.f, d = 0.f, t = 0.f;
#pragma unroll
            for (int k = 0; k < DH; k++) {
                float wv = wrow[k];
                s += wv * av[k]; d += wv * dv[k]; t += wv * mv[k];
            }
            smem[OFF_WS + f * 4 + hh] = s;
            smem[OFF_WD + f * 4 + hh] = d;
            smem[OFF_WT + f * 4 + hh] = t;
        }
        // bconst = bias . me (warp 0)
        if (tid < 32) {
            float v = bias[tid] * me[tid] + bias[tid + 32] * me[tid + 32];
#pragma unroll
            for (int o = 16; o > 0; o >>= 1) v += __shfl_xor_sync(0xffffffffu, v, o);
            if (tid == 0) smem[OFF_BC] = v;
        }
        asm volatile("bar.sync 1, 256;" ::: "memory");

        // ---- Phase C: broadcast-weight GEMM. Thread owns 2 nodes, all heads. ----
        {
            const int n0 = tid;           // 0..255
            int n1 = tid + 256;           // 256..511
            const bool v1 = (n1 < NPG);
            if (!v1) n1 = NPG - 1;
            const float* xr0 = xs + n0 * 68;
            const float* xr1 = xs + n1 * 68;
            const float4* ws4 = (const float4*)(smem + OFF_WS);
            const float4* wd4 = (const float4*)(smem + OFF_WD);
            const float4* wt4 = (const float4*)(smem + OFF_WT);
            float4 as0 = {0,0,0,0}, ad0 = {0,0,0,0}, tt0 = {0,0,0,0};
            float4 as1 = {0,0,0,0}, ad1 = {0,0,0,0}, tt1 = {0,0,0,0};
#pragma unroll
            for (int f4 = 0; f4 < 16; f4++) {
                float4 x0 = *(const float4*)(xr0 + f4 * 4);
                float4 x1 = *(const float4*)(xr1 + f4 * 4);
#pragma unroll
                for (int j = 0; j < 4; j++) {
                    float xf0 = (j == 0) ? x0.x : (j == 1) ? x0.y : (j == 2) ? x0.z : x0.w;
                    float xf1 = (j == 0) ? x1.x : (j == 1) ? x1.y : (j == 2) ? x1.z : x1.w;
                    float4 w1 = ws4[f4 * 4 + j];   // broadcast (same addr all lanes)
                    float4 w2 = wd4[f4 * 4 + j];
                    float4 w3 = wt4[f4 * 4 + j];
                    as0.x += xf0 * w1.x; as0.y += xf0 * w1.y; as0.z += xf0 * w1.z; as0.w += xf0 * w1.w;
                    ad0.x += xf0 * w2.x; ad0.y += xf0 * w2.y; ad0.z += xf0 * w2.z; ad0.w += xf0 * w2.w;
                    tt0.x += xf0 * w3.x; tt0.y += xf0 * w3.y; tt0.z += xf0 * w3.z; tt0.w += xf0 * w3.w;
                    as1.x += xf1 * w1.x; as1.y += xf1 * w1.y; as1.z += xf1 * w1.z; as1.w += xf1 * w1.w;
                    ad1.x += xf1 * w2.x; ad1.y += xf1 * w2.y; ad1.z += xf1 * w2.z; ad1.w += xf1 * w2.w;
                    tt1.x += xf1 * w3.x; tt1.y += xf1 * w3.y; tt1.z += xf1 * w3.z; tt1.w += xf1 * w3.w;
                }
            }
            *(float4*)&A_s4f[n0 * 4] = as0;
            *(float4*)&A_d4f[n0 * 4] = ad0;
            *(float4*)&T4f[n0 * 4] = tt0;
            if (v1) {
                *(float4*)&A_s4f[n1 * 4] = as1;
                *(float4*)&A_d4f[n1 * 4] = ad1;
                *(float4*)&T4f[n1 * 4] = tt1;
            }
        }

        // ---- GEMM warps join scatter on edge tail [ESPLIT4, 2000) ----
        for (int i = ESPLIT4 + tid; i < EPG / 4; i += 256) {
            int4 s4 = ((const int4*)(esrc + ebase))[i];
            int4 d4 = ((const int4*)(edst + ebase))[i];
            int d0 = d4.x - nbase, d1 = d4.y - nbase,
                d2 = d4.z - nbase, d3 = d4.w - nbase;
            int p0 = atomicAdd(&cur[d0], 1);
            if (p0 < BCAP) buck[d0 * BCAP + p0] = (unsigned short)(s4.x - nbase);
            int p1 = atomicAdd(&cur[d1], 1);
            if (p1 < BCAP) buck[d1 * BCAP + p1] = (unsigned short)(s4.y - nbase);
            int p2 = atomicAdd(&cur[d2], 1);
            if (p2 < BCAP) buck[d2 * BCAP + p2] = (unsigned short)(s4.z - nbase);
            int p3 = atomicAdd(&cur[d3], 1);
            if (p3 < BCAP) buck[d3 * BCAP + p3] = (unsigned short)(s4.w - nbase);
        }
    } else {
        // ================= Scatter side: warps 8-15, edges [0, ESPLIT4) =================
        const int lt = tid - 256;
        for (int i = lt; i < NPG; i += 256) cur[i] = 0;
        asm volatile("bar.sync 2, 256;" ::: "memory");
        for (int i = lt; i < ESPLIT4; i += 256) {
            int4 s4 = ((const int4*)(esrc + ebase))[i];
            int4 d4 = ((const int4*)(edst + ebase))[i];
            int d0 = d4.x - nbase, d1 = d4.y - nbase,
                d2 = d4.z - nbase, d3 = d4.w - nbase;
            int p0 = atomicAdd(&cur[d0], 1);
            if (p0 < BCAP) buck[d0 * BCAP + p0] = (unsigned short)(s4.x - nbase);
            int p1 = atomicAdd(&cur[d1], 1);
            if (p1 < BCAP) buck[d1 * BCAP + p1] = (unsigned short)(s4.y - nbase);
            int p2 = atomicAdd(&cur[d2], 1);
            if (p2 < BCAP) buck[d2 * BCAP + p2] = (unsigned short)(s4.z - nbase);
            int p3 = atomicAdd(&cur[d3], 1);
            if (p3 < BCAP) buck[d3 * BCAP + p3] = (unsigned short)(s4.w - nbase);
        }
    }
    __syncthreads();

    // ---- Gather: one thread per dst, 4 heads vectorized ----
    float v = -INFINITY;
    if (tid < NPG) {
        const int d = tid;
        int n = cur[d]; n = (n < BCAP) ? n : BCAP;
        const float4 ad4 = *(const float4*)&A_d4f[d * 4];
        const unsigned short* bk = buck + d * BCAP;
        float den0 = 0.f, den1 = 0.f, den2 = 0.f, den3 = 0.f;
        float ac0 = 0.f, ac1 = 0.f, ac2 = 0.f, ac3 = 0.f;
        for (int j = 0; j < n; j++) {
            const int s = bk[j];
            const float4 as4 = *(const float4*)&A_s4f[s * 4];
            const float4 t4 = *(const float4*)&T4f[s * 4];
            float e0 = as4.x + ad4.x; e0 = (e0 > 0.f) ? e0 : 0.2f * e0;
            float e1 = as4.y + ad4.y; e1 = (e1 > 0.f) ? e1 : 0.2f * e1;
            float e2 = as4.z + ad4.z; e2 = (e2 > 0.f) ? e2 : 0.2f * e2;
            float e3 = as4.w + ad4.w; e3 = (e3 > 0.f) ? e3 : 0.2f * e3;
            float x0 = __expf(e0), x1 = __expf(e1), x2 = __expf(e2), x3 = __expf(e3);
            den0 += x0; den1 += x1; den2 += x2; den3 += x3;
            ac0 += x0 * t4.x; ac1 += x1 * t4.y; ac2 += x2 * t4.z; ac3 += x3 * t4.w;
        }
        float r0 = (den0 > 0.f) ? __fdividef(ac0, den0) : 0.f;
        float r1 = (den1 > 0.f) ? __fdividef(ac1, den1) : 0.f;
        float r2 = (den2 > 0.f) ? __fdividef(ac2, den2) : 0.f;
        float r3 = (den3 > 0.f) ? __fdividef(ac3, den3) : 0.f;
        v = r0 + r1 + r2 + r3 + smem[OFF_BC];
    }

    // ---- log_softmax over 500 nodes ----
    __shared__ float lred[16];
    float m = v;
#pragma unroll
    for (int o = 16; o > 0; o >>= 1) m = fmaxf(m, __shfl_xor_sync(0xffffffffu, m, o));
    if ((tid & 31) == 0) lred[tid >> 5] = m;
    __syncthreads();
    if (tid < 32) {
        float t = (tid < 16) ? lred[tid] : -INFINITY;
#pragma unroll
        for (int o = 8; o > 0; o >>= 1) t = fmaxf(t, __shfl_xor_sync(0xffffffffu, t, o));
        if (tid == 0) lred[0] = t;
    }
    __syncthreads();
    m = lred[0];
    __syncthreads();
    float p = (tid < NPG) ? __expf(v - m) : 0.0f;
    float s = p;
#pragma unroll
    for (int o = 16; o > 0; o >>= 1) s += __shfl_xor_sync(0xffffffffu, s, o);
    if ((tid & 31) == 0) lred[tid >> 5] = s;
    __syncthreads();
    if (tid < 32) {
        float t = (tid < 16) ? lred[tid] : 0.0f;
#pragma unroll
        for (int o = 8; o > 0; o >>= 1) t += __shfl_xor_sync(0xffffffffu, t, o);
        if (tid == 0) lred[0] = t;
    }
    __syncthreads();
    const float lse = m + logf(lred[0]);
    if (tid < NPG) out[b * NPG + tid] = v - lse;
}

// ---------------- Launch ----------------
extern "C" void kernel_launch(void* const* d_in, const int* in_sizes, int n_in,
                              void* d_out, int out_size) {
    const float* message = (const float*)d_in[0];
    const float* x       = (const float*)d_in[1];
    const int*   esrc    = (const int*)d_in[2];
    const int*   edst    = (const int*)d_in[3];
    const float* W       = (const float*)d_in[4];
    const float* a_src   = (const float*)d_in[5];
    const float* a_dst   = (const float*)d_in[6];
    const float* bias    = (const float*)d_in[7];
    const float* fc_w    = (const float*)d_in[8];
    const float* fc_b    = (const float*)d_in[9];
    float* out = (float*)d_out;

    static int init = 0;
    if (!init) {
        cudaFuncSetAttribute(fused_kernel, cudaFuncAttributeMaxDynamicSharedMemorySize, SMEM_BYTES);
        init = 1;
    }

    fused_kernel<<<NB, NTH, SMEM_BYTES>>>(message, x, esrc, edst, W,
                                          a_src, a_dst, bias, fc_w, fc_b, out);
}